// round 14
// baseline (speedup 1.0000x reference)
#include <cuda_runtime.h>
#include <cuda_bf16.h>
#include <cstdint>

// Problem constants
#define NTOK   65536      // 16 * 64 * 64 tokens
#define DIM    256        // channels / code dim
#define NCODE  1024       // codebook entries
#define HW     4096       // 64*64
#define IMG_ELEMS 16777216 // 16*256*64*64

#define CAP    8          // candidate list capacity per token
#define DELTA  1.0f       // rescore margin on approx (bf16) distances — validated R5/R8/R13

#define NGATHER (IMG_ELEMS / (256 * 4))   // gather grid size

// ---------------------------------------------------------------------------
// Device scratch
// ---------------------------------------------------------------------------
__device__ float  g_e2[NCODE];
__device__ int    g_ind[NTOK];
__device__ double g_loss;
__device__ unsigned g_done;
__device__ __align__(16) __nv_bfloat16 g_ebt[(size_t)NCODE * DIM]; // e [code][d] bf16
__device__ __align__(16) float         g_ebtf[(size_t)NCODE * DIM];// e [code][d] fp32
__device__ int    g_cand[NTOK][CAP];
__device__ unsigned char g_ncand[NTOK];

// ---------------------------------------------------------------------------
// PTX helpers (sm_80+ features only: valid at generic sm_103 target)
// ---------------------------------------------------------------------------
__device__ __forceinline__ uint32_t smem_to_u32(const void* p) {
    uint32_t a;
    asm("{ .reg .u64 t; cvta.to.shared.u64 t, %1; cvt.u32.u64 %0, t; }" : "=r"(a) : "l"(p));
    return a;
}
__device__ __forceinline__ void ldsm_x4(uint32_t& r0, uint32_t& r1, uint32_t& r2,
                                        uint32_t& r3, uint32_t addr) {
    asm volatile("ldmatrix.sync.aligned.m8n8.x4.shared.b16 {%0,%1,%2,%3}, [%4];"
                 : "=r"(r0), "=r"(r1), "=r"(r2), "=r"(r3) : "r"(addr));
}
__device__ __forceinline__ void mma_bf16(float c[4], const uint32_t a[4],
                                         const uint32_t b[2]) {
    asm volatile("mma.sync.aligned.m16n8k16.row.col.f32.bf16.bf16.f32 "
                 "{%0,%1,%2,%3}, {%4,%5,%6,%7}, {%8,%9}, {%0,%1,%2,%3};"
                 : "+f"(c[0]), "+f"(c[1]), "+f"(c[2]), "+f"(c[3])
                 : "r"(a[0]), "r"(a[1]), "r"(a[2]), "r"(a[3]), "r"(b[0]), "r"(b[1]));
}
__device__ __forceinline__ void cp16(uint32_t dst, const void* src) {
    asm volatile("cp.async.cg.shared.global [%0], [%1], 16;" :: "r"(dst), "l"(src));
}
#define CP_COMMIT() asm volatile("cp.async.commit_group;" ::: "memory")
#define CP_WAIT(n)  asm volatile("cp.async.wait_group %0;" :: "n"(n) : "memory")

__device__ __forceinline__ uint16_t bf16bits(float v) {
    __nv_bfloat16 b = __float2bfloat16(v);
    return __bfloat16_as_ushort(b);
}

// monotone unsigned key for float ordering (handles negatives)
__device__ __forceinline__ unsigned long long packsc(float f, int col) {
    unsigned u = __float_as_uint(f);
    u ^= ((unsigned)((int)u >> 31)) | 0x80000000u;
    return ((unsigned long long)u << 32) | (unsigned)col;
}
__device__ __forceinline__ float unkeyf(unsigned u) {
    return (u & 0x80000000u) ? __uint_as_float(u ^ 0x80000000u)
                             : __uint_as_float(~u);
}

// ---------------------------------------------------------------------------
// Kernel A: per-code squared norms + zero loss/done
// ---------------------------------------------------------------------------
__global__ void e2_kernel(const float* __restrict__ embed) {
    int k = blockIdx.x * 256 + threadIdx.x;
    float s = 0.f;
    #pragma unroll 8
    for (int d = 0; d < DIM; ++d) {
        float v = embed[d * NCODE + k];
        s = fmaf(v, v, s);
    }
    g_e2[k] = s;
    if (k == 0) { g_loss = 0.0; g_done = 0u; }
}

// ---------------------------------------------------------------------------
// Kernel P: transpose embed [d][k] -> code-major (bf16 + fp32 copies)
// ---------------------------------------------------------------------------
__global__ void __launch_bounds__(256)
prep_e_kernel(const float* __restrict__ embed) {
    __shared__ float t[32][33];
    int d0 = blockIdx.y << 5;
    int k0 = blockIdx.x << 5;
    const float* src = embed + (size_t)d0 * NCODE + k0;
    #pragma unroll
    for (int i = 0; i < 32; i += 8)
        t[threadIdx.y + i][threadIdx.x] = src[(size_t)(threadIdx.y + i) * NCODE + threadIdx.x];
    __syncthreads();
    size_t obase = (size_t)k0 * DIM + d0;
    #pragma unroll
    for (int i = 0; i < 32; i += 8) {
        float v = t[threadIdx.x][threadIdx.y + i];
        size_t o = obase + (size_t)(threadIdx.y + i) * DIM + threadIdx.x;
        g_ebtf[o] = v;
        g_ebt[o]  = __float2bfloat16(v);
    }
}

// ---------------------------------------------------------------------------
// Stage 1: bf16 mma.sync scoring. M=64 tokens/CTA (grid 1024 kills the wave-
// quantization tail: 512 tiles/4 waves -> 1024 tiles/~7 waves of half cost).
// 8 warps (256 thr), warp grid 2M x 4N, warp tile 32x32 (2 mt x 4 n8) —
// identical per-warp fragment mapping to validated R5/R8/R13.
// N=128 codes/iter, K=256, 8 iters; B double-buffered via cp.async;
// A produced in-kernel (fused NCHW->bf16 transpose-quantize). 528B rows.
// ---------------------------------------------------------------------------
#define MTILE    64
#define LDA      528
#define S_A      0
#define S_B      33792          // 64*528
#define S_BSZ    67584          // 128*528
#define S_E2     168960         // S_B + 2*S_BSZ (4KB)
#define S_G1     173056         // 64 x ull
#define S_CNT    173568         // 64 x int
#define S_TOTAL  173824

__global__ void __launch_bounds__(256, 1)
vq_mma_kernel(const float* __restrict__ x) {
    extern __shared__ char smem[];
    const uint32_t sb  = smem_to_u32(smem);
    const int tid   = threadIdx.x;
    const int lane  = tid & 31;
    const int wid   = tid >> 5;
    const int warpM = wid >> 2;       // 0..1 -> rows warpM*32..+32
    const int warpN = wid & 3;        // 0..3 -> cols warpN*32..+32 per iter
    const int tok0  = blockIdx.x << 6;

    float* e2s = (float*)(smem + S_E2);
    unsigned long long* sG1 = (unsigned long long*)(smem + S_G1);
    int* scnt = (int*)(smem + S_CNT);

    // async-load B subtile 'sub' (128 codes x 256 bf16) into buffer
    auto load_B = [&](int buf, int sub) {
        const char* src = (const char*)(g_ebt + ((size_t)sub << 7) * DIM);
        uint32_t dst = sb + S_B + buf * S_BSZ;
        #pragma unroll
        for (int j = 0; j < 16; ++j) {
            int idx = tid + (j << 8);     // 0..4095 16B chunks
            int r = idx >> 5, c = idx & 31;
            cp16(dst + r * LDA + c * 16, src + r * 512 + c * 16);
        }
    };
    load_B(0, 0);
    CP_COMMIT();                        // group0 = B0

    // A tile: fused transpose-quantize x (NCHW fp32) -> smem [token][d] bf16.
    // 1024 4x4 blocks over 64 rows x 256 dims; coalesced float4 LDGs.
    {
        const int bimg = tok0 >> 12;
        const int hwb  = tok0 & 4095;
        const float* xb = x + (size_t)bimg * DIM * HW + hwb;
        #pragma unroll
        for (int j = 0; j < 4; ++j) {
            int bb = tid + (j << 8);          // 0..1023
            int x1 = bb & 7, x2 = (bb >> 3) & 3, x3 = (bb >> 5) & 15, x4 = bb >> 9;
            int h0 = 4 * x1 + 32 * x4;        // token-local row 0..60
            int d0 = 4 * x2 + 16 * x3;        // channel 0..252
            float4 v[4];
            #pragma unroll
            for (int i = 0; i < 4; ++i)
                v[i] = *(const float4*)(xb + (size_t)(d0 + i) * HW + h0);
            #pragma unroll
            for (int r = 0; r < 4; ++r) {
                float f0 = (r == 0) ? v[0].x : (r == 1) ? v[0].y : (r == 2) ? v[0].z : v[0].w;
                float f1 = (r == 0) ? v[1].x : (r == 1) ? v[1].y : (r == 2) ? v[1].z : v[1].w;
                float f2 = (r == 0) ? v[2].x : (r == 1) ? v[2].y : (r == 2) ? v[2].z : v[2].w;
                float f3 = (r == 0) ? v[3].x : (r == 1) ? v[3].y : (r == 2) ? v[3].z : v[3].w;
                uint2 pk;
                pk.x = (uint32_t)bf16bits(f0) | ((uint32_t)bf16bits(f1) << 16);
                pk.y = (uint32_t)bf16bits(f2) | ((uint32_t)bf16bits(f3) << 16);
                *(uint2*)(smem + S_A + (h0 + r) * LDA + d0 * 2) = pk;
            }
        }
    }

    #pragma unroll
    for (int j = 0; j < 4; ++j) e2s[tid + (j << 8)] = g_e2[tid + (j << 8)];
    if (tid < MTILE) sG1[tid] = 0xFFFFFFFFFFFFFFFFull;

    // per-thread top-2 per row-slot (4 slots: 2 mtiles x 2 row-halves)
    float b1v[4], b2v[4];
    int   k1v[4], k2v[4];
    #pragma unroll
    for (int s = 0; s < 4; ++s) { b1v[s] = 3.4e38f; b2v[s] = 3.4e38f; k1v[s] = 0; k2v[s] = 0; }

    // ldmatrix lane addressing (identical fragment mapping to validated rounds)
    uint32_t aA[2];
    #pragma unroll
    for (int mt = 0; mt < 2; ++mt)
        aA[mt] = sb + S_A
               + (uint32_t)((warpM * 32 + mt * 16 + (lane & 15)) * LDA)
               + (uint32_t)((lane >> 4) * 16);
    const uint32_t bRowOff =
        (uint32_t)((warpN * 32 + ((lane >> 4) & 1) * 8 + (lane & 7)) * LDA)
        + (uint32_t)(((lane >> 3) & 1) * 16);

    #pragma unroll 1
    for (int it = 0; it < 8; ++it) {
        int buf = it & 1;
        if (it + 1 < 8) { load_B(buf ^ 1, it + 1); CP_COMMIT(); CP_WAIT(1); }
        else            { CP_WAIT(0); }
        __syncthreads();

        float c[2][4][4];
        #pragma unroll
        for (int mt = 0; mt < 2; ++mt)
            #pragma unroll
            for (int nt = 0; nt < 4; ++nt)
                #pragma unroll
                for (int e = 0; e < 4; ++e) c[mt][nt][e] = 0.f;

        const uint32_t bBase = sb + S_B + buf * S_BSZ + bRowOff;

        #pragma unroll 4
        for (int k = 0; k < 256; k += 16) {
            uint32_t a[2][4];
            #pragma unroll
            for (int mt = 0; mt < 2; ++mt)
                ldsm_x4(a[mt][0], a[mt][1], a[mt][2], a[mt][3],
                        aA[mt] + (uint32_t)(k * 2));
            uint32_t b[4][2];
            #pragma unroll
            for (int p = 0; p < 2; ++p) {
                uint32_t r0, r1, r2, r3;
                ldsm_x4(r0, r1, r2, r3,
                        bBase + (uint32_t)(p * 16 * LDA) + (uint32_t)(k * 2));
                b[2 * p][0] = r0; b[2 * p][1] = r1;
                b[2 * p + 1][0] = r2; b[2 * p + 1][1] = r3;
            }
            #pragma unroll
            for (int mt = 0; mt < 2; ++mt)
                #pragma unroll
                for (int nt = 0; nt < 4; ++nt)
                    mma_bf16(c[mt][nt], a[mt], b[nt]);
        }

        // epilogue: fold scores into per-thread top-2 per row slot
        #pragma unroll
        for (int mt = 0; mt < 2; ++mt)
            #pragma unroll
            for (int nt = 0; nt < 4; ++nt)
                #pragma unroll
                for (int e = 0; e < 4; ++e) {
                    const int s   = mt * 2 + (e >> 1);
                    const int col = (it << 7) + warpN * 32 + nt * 8
                                  + 2 * (lane & 3) + (e & 1);
                    float sc = fmaf(-2.f, c[mt][nt][e], e2s[col]);
                    if (sc < b2v[s]) {
                        if (sc < b1v[s]) {
                            b2v[s] = b1v[s]; k2v[s] = k1v[s];
                            b1v[s] = sc;     k1v[s] = col;
                        } else { b2v[s] = sc; k2v[s] = col; }
                    }
                }
        __syncthreads();   // all warps done reading buf before overwrite
    }

    // ---- Block-exact merge across the 16 owners of each token row ----
    #pragma unroll
    for (int s = 0; s < 4; ++s) {
        const int lt = warpM * 32 + (s >> 1) * 16 + (s & 1) * 8 + (lane >> 2);
        atomicMin(&sG1[lt], packsc(b1v[s], k1v[s]));
    }
    __syncthreads();
    if (tid < MTILE) {
        g_cand[tok0 + tid][0] = (int)(sG1[tid] & 0xFFFFFFFFull);
        scnt[tid] = 1;
    }
    __syncthreads();
    #pragma unroll
    for (int s = 0; s < 4; ++s) {
        const int lt  = warpM * 32 + (s >> 1) * 16 + (s & 1) * 8 + (lane >> 2);
        const int tok = tok0 + lt;
        unsigned long long g = sG1[lt];
        int   gk = (int)(g & 0xFFFFFFFFull);
        float gv = unkeyf((unsigned)(g >> 32));
        if (k1v[s] != gk && b1v[s] < gv + DELTA) {
            int p = atomicAdd(&scnt[lt], 1);
            if (p < CAP) g_cand[tok][p] = k1v[s];
        }
        if (b2v[s] < gv + DELTA) {
            int p = atomicAdd(&scnt[lt], 1);
            if (p < CAP) g_cand[tok][p] = k2v[s];
        }
    }
    __syncthreads();
    if (tid < MTILE)
        g_ncand[tok0 + tid] = (unsigned char)(scnt[tid] < CAP ? scnt[tid] : CAP);
}

// ---------------------------------------------------------------------------
// Stage 2: exact fp32 rescore, block = 32 consecutive tokens (256 thr).
// x staged PREDICATED+coalesced from NCHW into smem (only multi-candidate
// token lanes fetch); warp w rescores tokens 4w..4w+3 lane-parallel (shfl).
// ---------------------------------------------------------------------------
__global__ void __launch_bounds__(256)
rescore_kernel(const float* __restrict__ x) {
    __shared__ float xs[32][257];     // [token-local][d], pad -> conflict-free
    const int wid = threadIdx.x >> 5;
    const int lid = threadIdx.x & 31;
    const int tok0 = blockIdx.x << 5;         // 32 tokens, same image (32 | 4096)
    const int bimg = tok0 >> 12;
    const int hw0  = tok0 & 4095;

    // my lane's token needs staging iff it has >1 candidates
    const bool need = (g_ncand[tok0 + lid] > 1);

    // predicated coalesced staging: warp w loads channel d = wid + 8j
    {
        const float* xb = x + (size_t)bimg * DIM * HW + hw0;
        #pragma unroll 8
        for (int j = 0; j < 32; ++j) {
            int d = wid + (j << 3);
            if (need) xs[lid][d] = xb[(size_t)d * HW + lid];
        }
    }
    __syncthreads();

    #pragma unroll 1
    for (int tt = 0; tt < 4; ++tt) {
        const int lt  = (wid << 2) + tt;
        const int tok = tok0 + lt;
        int n = g_ncand[tok];
        if (n <= 1) {
            if (lid == 0) g_ind[tok] = g_cand[tok][0];
            continue;
        }

        float bs = 3.4e38f;
        int   bk = 0x7fffffff;
        #pragma unroll 1
        for (int i = 0; i < n; ++i) {
            int k = g_cand[tok][i];
            const float* er = g_ebtf + (size_t)k * DIM;
            float acc = 0.f;
            #pragma unroll
            for (int j = 0; j < 8; ++j)
                acc = fmaf(xs[lt][lid + (j << 5)], er[lid + (j << 5)], acc);
            #pragma unroll
            for (int off = 16; off > 0; off >>= 1)
                acc += __shfl_xor_sync(0xffffffffu, acc, off);
            float s = fmaf(-2.f, acc, g_e2[k]);
            if (s < bs || (s == bs && k < bk)) { bs = s; bk = k; }
        }
        if (lid == 0) g_ind[tok] = bk;
    }
}

// ---------------------------------------------------------------------------
// Kernel C: gather to NCHW output + MSE loss + fused finalize (last block).
// ---------------------------------------------------------------------------
__global__ void __launch_bounds__(256)
gather_kernel(const float* __restrict__ x, const float* __restrict__ embed,
              float* __restrict__ outImg, float* __restrict__ outLoss) {
    size_t g = (((size_t)blockIdx.x << 8) + threadIdx.x) << 2;
    int n   = (int)(g >> 20);
    int rem = (int)(g & 1048575);
    int d   = rem >> 12;
    int hw  = rem & 4095;
    int tok = (n << 12) + hw;

    const float* erow = embed + d * NCODE;
    float q0 = erow[g_ind[tok + 0]];
    float q1 = erow[g_ind[tok + 1]];
    float q2 = erow[g_ind[tok + 2]];
    float q3 = erow[g_ind[tok + 3]];

    float4 xv = *(const float4*)(x + g);

    // scalar stores: outImg = d_out + 1 is only 4-byte aligned
    outImg[g + 0] = q0;
    outImg[g + 1] = q1;
    outImg[g + 2] = q2;
    outImg[g + 3] = q3;

    float d0 = q0 - xv.x, d1 = q1 - xv.y, d2 = q2 - xv.z, d3 = q3 - xv.w;
    float local = d0 * d0 + d1 * d1 + d2 * d2 + d3 * d3;

    #pragma unroll
    for (int off = 16; off > 0; off >>= 1)
        local += __shfl_down_sync(0xffffffffu, local, off);
    __shared__ float warpsum[8];
    int wid = threadIdx.x >> 5, lid = threadIdx.x & 31;
    if (lid == 0) warpsum[wid] = local;
    __syncthreads();
    if (threadIdx.x == 0) {
        float s = 0.f;
        #pragma unroll
        for (int w = 0; w < 8; ++w) s += warpsum[w];
        atomicAdd(&g_loss, (double)s);
        __threadfence();
        unsigned t = atomicInc(&g_done, 0xffffffffu);
        if (t == NGATHER - 1 && outLoss) {
            double total = atomicAdd(&g_loss, 0.0);   // ordered read
            outLoss[0] = (float)(0.25 * total / (double)IMG_ELEMS);
        }
    }
}

// ---------------------------------------------------------------------------
extern "C" void kernel_launch(void* const* d_in, const int* in_sizes, int n_in,
                              void* d_out, int out_size) {
    const float* x     = (const float*)d_in[0];   // [16,256,64,64] fp32
    const float* embed = (const float*)d_in[1];   // [256,1024] fp32
    float* out = (float*)d_out;

    int off = out_size - IMG_ELEMS;               // expected 1 (loss scalar first)
    float* outImg  = out + (off > 0 ? off : 0);
    float* outLoss = (off > 0) ? out : nullptr;

    cudaFuncSetAttribute(vq_mma_kernel,
                         cudaFuncAttributeMaxDynamicSharedMemorySize, S_TOTAL);

    e2_kernel<<<NCODE / 256, 256>>>(embed);
    prep_e_kernel<<<dim3(NCODE / 32, DIM / 32, 1), dim3(32, 8)>>>(embed);
    vq_mma_kernel<<<NTOK / MTILE, 256, S_TOTAL>>>(x);
    rescore_kernel<<<NTOK / 32, 256>>>(x);
    gather_kernel<<<NGATHER, 256>>>(x, embed, outImg, outLoss);
}

// round 16
// speedup vs baseline: 1.0770x; 1.0770x over previous
#include <cuda_runtime.h>
#include <cuda_bf16.h>
#include <cstdint>

// Problem constants
#define NTOK   65536      // 16 * 64 * 64 tokens
#define DIM    256        // channels / code dim
#define NCODE  1024       // codebook entries
#define HW     4096       // 64*64
#define IMG_ELEMS 16777216 // 16*256*64*64

#define CAP    8          // candidate list capacity per token
#define DELTA  1.0f       // rescore margin on approx (bf16) distances — validated R5/R8/R13

#define NGATHER (IMG_ELEMS / (256 * 4))   // gather grid size

// ---------------------------------------------------------------------------
// Device scratch
// ---------------------------------------------------------------------------
__device__ float  g_e2[NCODE];
__device__ int    g_ind[NTOK];
__device__ double g_loss;
__device__ unsigned g_done;
__device__ __align__(16) __nv_bfloat16 g_ebt[(size_t)NCODE * DIM]; // e [code][d] bf16
__device__ __align__(16) float         g_ebtf[(size_t)NCODE * DIM];// e [code][d] fp32

// ---------------------------------------------------------------------------
// PTX helpers (sm_80+ features only: valid at generic sm_103 target)
// ---------------------------------------------------------------------------
__device__ __forceinline__ uint32_t smem_to_u32(const void* p) {
    uint32_t a;
    asm("{ .reg .u64 t; cvta.to.shared.u64 t, %1; cvt.u32.u64 %0, t; }" : "=r"(a) : "l"(p));
    return a;
}
__device__ __forceinline__ void ldsm_x4(uint32_t& r0, uint32_t& r1, uint32_t& r2,
                                        uint32_t& r3, uint32_t addr) {
    asm volatile("ldmatrix.sync.aligned.m8n8.x4.shared.b16 {%0,%1,%2,%3}, [%4];"
                 : "=r"(r0), "=r"(r1), "=r"(r2), "=r"(r3) : "r"(addr));
}
__device__ __forceinline__ void mma_bf16(float c[4], const uint32_t a[4],
                                         const uint32_t b[2]) {
    asm volatile("mma.sync.aligned.m16n8k16.row.col.f32.bf16.bf16.f32 "
                 "{%0,%1,%2,%3}, {%4,%5,%6,%7}, {%8,%9}, {%0,%1,%2,%3};"
                 : "+f"(c[0]), "+f"(c[1]), "+f"(c[2]), "+f"(c[3])
                 : "r"(a[0]), "r"(a[1]), "r"(a[2]), "r"(a[3]), "r"(b[0]), "r"(b[1]));
}
__device__ __forceinline__ void cp16(uint32_t dst, const void* src) {
    asm volatile("cp.async.cg.shared.global [%0], [%1], 16;" :: "r"(dst), "l"(src));
}
#define CP_COMMIT() asm volatile("cp.async.commit_group;" ::: "memory")
#define CP_WAIT(n)  asm volatile("cp.async.wait_group %0;" :: "n"(n) : "memory")

__device__ __forceinline__ uint16_t bf16bits(float v) {
    __nv_bfloat16 b = __float2bfloat16(v);
    return __bfloat16_as_ushort(b);
}

// monotone unsigned key for float ordering (handles negatives)
__device__ __forceinline__ unsigned long long packsc(float f, int col) {
    unsigned u = __float_as_uint(f);
    u ^= ((unsigned)((int)u >> 31)) | 0x80000000u;
    return ((unsigned long long)u << 32) | (unsigned)col;
}
__device__ __forceinline__ float unkeyf(unsigned u) {
    return (u & 0x80000000u) ? __uint_as_float(u ^ 0x80000000u)
                             : __uint_as_float(~u);
}

// ---------------------------------------------------------------------------
// Kernel A: per-code squared norms + zero loss/done
// ---------------------------------------------------------------------------
__global__ void e2_kernel(const float* __restrict__ embed) {
    int k = blockIdx.x * 256 + threadIdx.x;
    float s = 0.f;
    #pragma unroll 8
    for (int d = 0; d < DIM; ++d) {
        float v = embed[d * NCODE + k];
        s = fmaf(v, v, s);
    }
    g_e2[k] = s;
    if (k == 0) { g_loss = 0.0; g_done = 0u; }
}

// ---------------------------------------------------------------------------
// Kernel P: transpose embed [d][k] -> code-major (bf16 + fp32 copies)
// ---------------------------------------------------------------------------
__global__ void __launch_bounds__(256)
prep_e_kernel(const float* __restrict__ embed) {
    __shared__ float t[32][33];
    int d0 = blockIdx.y << 5;
    int k0 = blockIdx.x << 5;
    const float* src = embed + (size_t)d0 * NCODE + k0;
    #pragma unroll
    for (int i = 0; i < 32; i += 8)
        t[threadIdx.y + i][threadIdx.x] = src[(size_t)(threadIdx.y + i) * NCODE + threadIdx.x];
    __syncthreads();
    size_t obase = (size_t)k0 * DIM + d0;
    #pragma unroll
    for (int i = 0; i < 32; i += 8) {
        float v = t[threadIdx.x][threadIdx.y + i];
        size_t o = obase + (size_t)(threadIdx.y + i) * DIM + threadIdx.x;
        g_ebtf[o] = v;
        g_ebt[o]  = __float2bfloat16(v);
    }
}

// ---------------------------------------------------------------------------
// Stage 1+2 FUSED: bf16 mma.sync scoring (R13 core: M=128, 16 warps, grid
// 512) + in-kernel candidate merge + in-kernel exact fp32 rescore.
// After the final MMA iter, A/B0 smem is dead: stage the CTA's 128 tokens of
// exact fp32 x there (coalesced, predicated per token row) and rescore
// multi-candidate tokens with the R13-validated arithmetic, writing g_ind.
// ---------------------------------------------------------------------------
#define LDA      528
#define S_A      0
#define S_B      67584          // 128*528
#define S_BSZ    67584
#define S_E2     202752         // S_B + 2*S_BSZ (4KB)
#define S_G1     206848         // 128 x ull
#define S_CNT    207872         // 128 x int
#define S_CAND   208384         // 128 x CAP ints (4KB)
#define S_TOTAL  212480
// fp32 x staging (aliases A+B0 region, used only after last MMA): row stride
// 257 floats => 128 rows * 1028B = 131584 <= 202752. Bank-conflict-free.
#define XROW     257

__global__ void __launch_bounds__(512, 1)
vq_mma_kernel(const float* __restrict__ x) {
    extern __shared__ char smem[];
    const uint32_t sb  = smem_to_u32(smem);
    const int tid   = threadIdx.x;
    const int lane  = tid & 31;
    const int wid   = tid >> 5;
    const int warpM = wid >> 2;       // 0..3 -> rows warpM*32..+32
    const int warpN = wid & 3;        // 0..3 -> cols warpN*32..+32 per iter
    const int tok0  = blockIdx.x << 7;

    float* e2s = (float*)(smem + S_E2);
    unsigned long long* sG1 = (unsigned long long*)(smem + S_G1);
    int* scnt  = (int*)(smem + S_CNT);
    int (*scand)[CAP] = (int (*)[CAP])(smem + S_CAND);
    float* xs32 = (float*)smem;       // staged fp32 x, [row * XROW + d]

    // async-load B subtile 'sub' (128 codes x 256 bf16) into buffer
    auto load_B = [&](int buf, int sub) {
        const char* src = (const char*)(g_ebt + ((size_t)sub << 7) * DIM);
        uint32_t dst = sb + S_B + buf * S_BSZ;
        #pragma unroll
        for (int j = 0; j < 8; ++j) {
            int idx = tid + (j << 9);     // 0..4095 16B chunks
            int r = idx >> 5, c = idx & 31;
            cp16(dst + r * LDA + c * 16, src + r * 512 + c * 16);
        }
    };
    load_B(0, 0);
    CP_COMMIT();                        // group0 = B0

    // A tile: fused transpose-quantize x (NCHW fp32) -> smem [token][d] bf16.
    // 4x4 blocks (validated R12/R13 addressing): coalesced float4 LDGs.
    const int bimg = tok0 >> 12;
    const int hwb  = tok0 & 4095;
    const float* xb = x + (size_t)bimg * DIM * HW + hwb;
    {
        #pragma unroll
        for (int j = 0; j < 4; ++j) {
            int bb = tid + (j << 9);
            int x1 = bb & 7, x2 = (bb >> 3) & 3, x3 = (bb >> 5) & 15, x4 = bb >> 9;
            int h0 = 4 * x1 + 32 * x4;     // token-local row
            int d0 = 4 * x2 + 16 * x3;     // channel
            float4 v[4];
            #pragma unroll
            for (int i = 0; i < 4; ++i)
                v[i] = *(const float4*)(xb + (size_t)(d0 + i) * HW + h0);
            #pragma unroll
            for (int r = 0; r < 4; ++r) {
                float f0 = (r == 0) ? v[0].x : (r == 1) ? v[0].y : (r == 2) ? v[0].z : v[0].w;
                float f1 = (r == 0) ? v[1].x : (r == 1) ? v[1].y : (r == 2) ? v[1].z : v[1].w;
                float f2 = (r == 0) ? v[2].x : (r == 1) ? v[2].y : (r == 2) ? v[2].z : v[2].w;
                float f3 = (r == 0) ? v[3].x : (r == 1) ? v[3].y : (r == 2) ? v[3].z : v[3].w;
                uint2 pk;
                pk.x = (uint32_t)bf16bits(f0) | ((uint32_t)bf16bits(f1) << 16);
                pk.y = (uint32_t)bf16bits(f2) | ((uint32_t)bf16bits(f3) << 16);
                *(uint2*)(smem + S_A + (h0 + r) * LDA + d0 * 2) = pk;
            }
        }
    }

    #pragma unroll
    for (int j = 0; j < 2; ++j) e2s[tid + (j << 9)] = g_e2[tid + (j << 9)];
    if (tid < 128) sG1[tid] = 0xFFFFFFFFFFFFFFFFull;

    // per-thread top-2 per row-slot (4 slots: 2 mtiles x 2 row-halves)
    float b1v[4], b2v[4];
    int   k1v[4], k2v[4];
    #pragma unroll
    for (int s = 0; s < 4; ++s) { b1v[s] = 3.4e38f; b2v[s] = 3.4e38f; k1v[s] = 0; k2v[s] = 0; }

    // ldmatrix lane addressing (identical fragment mapping to validated rounds)
    uint32_t aA[2];
    #pragma unroll
    for (int mt = 0; mt < 2; ++mt)
        aA[mt] = sb + S_A
               + (uint32_t)((warpM * 32 + mt * 16 + (lane & 15)) * LDA)
               + (uint32_t)((lane >> 4) * 16);
    const uint32_t bRowOff =
        (uint32_t)((warpN * 32 + ((lane >> 4) & 1) * 8 + (lane & 7)) * LDA)
        + (uint32_t)(((lane >> 3) & 1) * 16);

    #pragma unroll 1
    for (int it = 0; it < 8; ++it) {
        int buf = it & 1;
        if (it + 1 < 8) { load_B(buf ^ 1, it + 1); CP_COMMIT(); CP_WAIT(1); }
        else            { CP_WAIT(0); }
        __syncthreads();

        float c[2][4][4];
        #pragma unroll
        for (int mt = 0; mt < 2; ++mt)
            #pragma unroll
            for (int nt = 0; nt < 4; ++nt)
                #pragma unroll
                for (int e = 0; e < 4; ++e) c[mt][nt][e] = 0.f;

        const uint32_t bBase = sb + S_B + buf * S_BSZ + bRowOff;

        #pragma unroll 4
        for (int k = 0; k < 256; k += 16) {
            uint32_t a[2][4];
            #pragma unroll
            for (int mt = 0; mt < 2; ++mt)
                ldsm_x4(a[mt][0], a[mt][1], a[mt][2], a[mt][3],
                        aA[mt] + (uint32_t)(k * 2));
            uint32_t b[4][2];
            #pragma unroll
            for (int p = 0; p < 2; ++p) {
                uint32_t r0, r1, r2, r3;
                ldsm_x4(r0, r1, r2, r3,
                        bBase + (uint32_t)(p * 16 * LDA) + (uint32_t)(k * 2));
                b[2 * p][0] = r0; b[2 * p][1] = r1;
                b[2 * p + 1][0] = r2; b[2 * p + 1][1] = r3;
            }
            #pragma unroll
            for (int mt = 0; mt < 2; ++mt)
                #pragma unroll
                for (int nt = 0; nt < 4; ++nt)
                    mma_bf16(c[mt][nt], a[mt], b[nt]);
        }

        // epilogue: fold scores into per-thread top-2 per row slot
        #pragma unroll
        for (int mt = 0; mt < 2; ++mt)
            #pragma unroll
            for (int nt = 0; nt < 4; ++nt)
                #pragma unroll
                for (int e = 0; e < 4; ++e) {
                    const int s   = mt * 2 + (e >> 1);
                    const int col = (it << 7) + warpN * 32 + nt * 8
                                  + 2 * (lane & 3) + (e & 1);
                    float sc = fmaf(-2.f, c[mt][nt][e], e2s[col]);
                    if (sc < b2v[s]) {
                        if (sc < b1v[s]) {
                            b2v[s] = b1v[s]; k2v[s] = k1v[s];
                            b1v[s] = sc;     k1v[s] = col;
                        } else { b2v[s] = sc; k2v[s] = col; }
                    }
                }
        __syncthreads();   // all warps done reading buf (and A on last iter)
    }

    // ---- Block-exact merge across the 16 owners of each token row ----
    #pragma unroll
    for (int s = 0; s < 4; ++s) {
        const int lt = warpM * 32 + (s >> 1) * 16 + (s & 1) * 8 + (lane >> 2);
        atomicMin(&sG1[lt], packsc(b1v[s], k1v[s]));
    }
    __syncthreads();
    if (tid < 128) {
        scand[tid][0] = (int)(sG1[tid] & 0xFFFFFFFFull);
        scnt[tid] = 1;
    }
    __syncthreads();
    #pragma unroll
    for (int s = 0; s < 4; ++s) {
        const int lt  = warpM * 32 + (s >> 1) * 16 + (s & 1) * 8 + (lane >> 2);
        unsigned long long g = sG1[lt];
        int   gk = (int)(g & 0xFFFFFFFFull);
        float gv = unkeyf((unsigned)(g >> 32));
        if (k1v[s] != gk && b1v[s] < gv + DELTA) {
            int p = atomicAdd(&scnt[lt], 1);
            if (p < CAP) scand[lt][p] = k1v[s];
        }
        if (b2v[s] < gv + DELTA) {
            int p = atomicAdd(&scnt[lt], 1);
            if (p < CAP) scand[lt][p] = k2v[s];
        }
    }
    __syncthreads();

    // ---- Fused exact rescore (R13 arithmetic) ----
    // Stage exact fp32 x into the dead A/B0 region, predicated per token row.
    // Warp layout: rg = wid & 3 (row group of 32 tokens), dbase = wid >> 2.
    {
        const int rg    = wid & 3;
        const int row   = rg * 32 + lane;
        const bool need = (scnt[row] > 1 && scnt[row] <= CAP) || (scnt[row] > 1);
        const int dbase = (wid >> 2) * 64;
        if (need) {
            #pragma unroll 8
            for (int j = 0; j < 64; ++j) {
                int d = dbase + j;
                xs32[row * XROW + d] = xb[(size_t)d * HW + rg * 32 + lane];
            }
        }
    }
    __syncthreads();

    // warp per token: warp w handles tokens w*8 .. w*8+7
    #pragma unroll 1
    for (int t = 0; t < 8; ++t) {
        const int lt  = (wid << 3) + t;
        const int tok = tok0 + lt;
        int n = scnt[lt];
        if (n > CAP) n = CAP;
        if (n <= 1) {
            if (lane == 0) g_ind[tok] = scand[lt][0];
            continue;
        }
        float bs = 3.4e38f;
        int   bk = 0x7fffffff;
        #pragma unroll 1
        for (int i = 0; i < n; ++i) {
            int k = scand[lt][i];
            const float* er = g_ebtf + (size_t)k * DIM;
            float acc = 0.f;
            #pragma unroll
            for (int j = 0; j < 8; ++j)
                acc = fmaf(xs32[lt * XROW + lane + (j << 5)], er[lane + (j << 5)], acc);
            #pragma unroll
            for (int off = 16; off > 0; off >>= 1)
                acc += __shfl_xor_sync(0xffffffffu, acc, off);
            float s = fmaf(-2.f, acc, e2s[k]);
            if (s < bs || (s == bs && k < bk)) { bs = s; bk = k; }
        }
        if (lane == 0) g_ind[tok] = bk;
    }
}

// ---------------------------------------------------------------------------
// Kernel C: gather to NCHW output + MSE loss + fused finalize (last block).
// ---------------------------------------------------------------------------
__global__ void __launch_bounds__(256)
gather_kernel(const float* __restrict__ x, const float* __restrict__ embed,
              float* __restrict__ outImg, float* __restrict__ outLoss) {
    size_t g = (((size_t)blockIdx.x << 8) + threadIdx.x) << 2;
    int n   = (int)(g >> 20);
    int rem = (int)(g & 1048575);
    int d   = rem >> 12;
    int hw  = rem & 4095;
    int tok = (n << 12) + hw;

    const float* erow = embed + d * NCODE;
    float q0 = erow[g_ind[tok + 0]];
    float q1 = erow[g_ind[tok + 1]];
    float q2 = erow[g_ind[tok + 2]];
    float q3 = erow[g_ind[tok + 3]];

    float4 xv = *(const float4*)(x + g);

    // scalar stores: outImg = d_out + 1 is only 4-byte aligned
    outImg[g + 0] = q0;
    outImg[g + 1] = q1;
    outImg[g + 2] = q2;
    outImg[g + 3] = q3;

    float d0 = q0 - xv.x, d1 = q1 - xv.y, d2 = q2 - xv.z, d3 = q3 - xv.w;
    float local = d0 * d0 + d1 * d1 + d2 * d2 + d3 * d3;

    #pragma unroll
    for (int off = 16; off > 0; off >>= 1)
        local += __shfl_down_sync(0xffffffffu, local, off);
    __shared__ float warpsum[8];
    int wid = threadIdx.x >> 5, lid = threadIdx.x & 31;
    if (lid == 0) warpsum[wid] = local;
    __syncthreads();
    if (threadIdx.x == 0) {
        float s = 0.f;
        #pragma unroll
        for (int w = 0; w < 8; ++w) s += warpsum[w];
        atomicAdd(&g_loss, (double)s);
        __threadfence();
        unsigned t = atomicInc(&g_done, 0xffffffffu);
        if (t == NGATHER - 1 && outLoss) {
            double total = atomicAdd(&g_loss, 0.0);   // ordered read
            outLoss[0] = (float)(0.25 * total / (double)IMG_ELEMS);
        }
    }
}

// ---------------------------------------------------------------------------
extern "C" void kernel_launch(void* const* d_in, const int* in_sizes, int n_in,
                              void* d_out, int out_size) {
    const float* x     = (const float*)d_in[0];   // [16,256,64,64] fp32
    const float* embed = (const float*)d_in[1];   // [256,1024] fp32
    float* out = (float*)d_out;

    int off = out_size - IMG_ELEMS;               // expected 1 (loss scalar first)
    float* outImg  = out + (off > 0 ? off : 0);
    float* outLoss = (off > 0) ? out : nullptr;

    cudaFuncSetAttribute(vq_mma_kernel,
                         cudaFuncAttributeMaxDynamicSharedMemorySize, S_TOTAL);

    e2_kernel<<<NCODE / 256, 256>>>(embed);
    prep_e_kernel<<<dim3(NCODE / 32, DIM / 32, 1), dim3(32, 8)>>>(embed);
    vq_mma_kernel<<<NTOK / 128, 512, S_TOTAL>>>(x);
    gather_kernel<<<NGATHER, 256>>>(x, embed, outImg, outLoss);
}

// round 17
// speedup vs baseline: 1.1096x; 1.0302x over previous
#include <cuda_runtime.h>
#include <cuda_bf16.h>
#include <cstdint>

// Problem constants
#define NTOK   65536      // 16 * 64 * 64 tokens
#define DIM    256        // channels / code dim
#define NCODE  1024       // codebook entries
#define HW     4096       // 64*64
#define IMG_ELEMS 16777216 // 16*256*64*64

#define CAP    8          // candidate list capacity per token
#define DELTA  1.0f       // rescore margin on approx (bf16) distances — validated R5/R8/R13

#define NGATHER (IMG_ELEMS / (256 * 4))   // gather grid size

// ---------------------------------------------------------------------------
// Device scratch
// ---------------------------------------------------------------------------
__device__ float  g_e2[NCODE];
__device__ __align__(16) int g_ind[NTOK];
__device__ double g_loss;
__device__ unsigned g_done;
__device__ __align__(16) __nv_bfloat16 g_ebt[(size_t)NCODE * DIM]; // e [code][d] bf16
__device__ __align__(16) float         g_ebtf[(size_t)NCODE * DIM];// e [code][d] fp32

// ---------------------------------------------------------------------------
// PTX helpers (sm_80+ features only: valid at generic sm_103 target)
// ---------------------------------------------------------------------------
__device__ __forceinline__ uint32_t smem_to_u32(const void* p) {
    uint32_t a;
    asm("{ .reg .u64 t; cvta.to.shared.u64 t, %1; cvt.u32.u64 %0, t; }" : "=r"(a) : "l"(p));
    return a;
}
__device__ __forceinline__ void ldsm_x4(uint32_t& r0, uint32_t& r1, uint32_t& r2,
                                        uint32_t& r3, uint32_t addr) {
    asm volatile("ldmatrix.sync.aligned.m8n8.x4.shared.b16 {%0,%1,%2,%3}, [%4];"
                 : "=r"(r0), "=r"(r1), "=r"(r2), "=r"(r3) : "r"(addr));
}
__device__ __forceinline__ void mma_bf16(float c[4], const uint32_t a[4],
                                         const uint32_t b[2]) {
    asm volatile("mma.sync.aligned.m16n8k16.row.col.f32.bf16.bf16.f32 "
                 "{%0,%1,%2,%3}, {%4,%5,%6,%7}, {%8,%9}, {%0,%1,%2,%3};"
                 : "+f"(c[0]), "+f"(c[1]), "+f"(c[2]), "+f"(c[3])
                 : "r"(a[0]), "r"(a[1]), "r"(a[2]), "r"(a[3]), "r"(b[0]), "r"(b[1]));
}
__device__ __forceinline__ void cp16(uint32_t dst, const void* src) {
    asm volatile("cp.async.cg.shared.global [%0], [%1], 16;" :: "r"(dst), "l"(src));
}
#define CP_COMMIT() asm volatile("cp.async.commit_group;" ::: "memory")
#define CP_WAIT(n)  asm volatile("cp.async.wait_group %0;" :: "n"(n) : "memory")

__device__ __forceinline__ uint16_t bf16bits(float v) {
    __nv_bfloat16 b = __float2bfloat16(v);
    return __bfloat16_as_ushort(b);
}

// monotone unsigned key for float ordering (handles negatives)
__device__ __forceinline__ unsigned long long packsc(float f, int col) {
    unsigned u = __float_as_uint(f);
    u ^= ((unsigned)((int)u >> 31)) | 0x80000000u;
    return ((unsigned long long)u << 32) | (unsigned)col;
}
__device__ __forceinline__ float unkeyf(unsigned u) {
    return (u & 0x80000000u) ? __uint_as_float(u ^ 0x80000000u)
                             : __uint_as_float(~u);
}

// ---------------------------------------------------------------------------
// Kernel A: per-code squared norms + zero loss/done
// ---------------------------------------------------------------------------
__global__ void e2_kernel(const float* __restrict__ embed) {
    int k = blockIdx.x * 256 + threadIdx.x;
    float s = 0.f;
    #pragma unroll 8
    for (int d = 0; d < DIM; ++d) {
        float v = embed[d * NCODE + k];
        s = fmaf(v, v, s);
    }
    g_e2[k] = s;
    if (k == 0) { g_loss = 0.0; g_done = 0u; }
}

// ---------------------------------------------------------------------------
// Kernel P: transpose embed [d][k] -> code-major (bf16 + fp32 copies)
// ---------------------------------------------------------------------------
__global__ void __launch_bounds__(256)
prep_e_kernel(const float* __restrict__ embed) {
    __shared__ float t[32][33];
    int d0 = blockIdx.y << 5;
    int k0 = blockIdx.x << 5;
    const float* src = embed + (size_t)d0 * NCODE + k0;
    #pragma unroll
    for (int i = 0; i < 32; i += 8)
        t[threadIdx.y + i][threadIdx.x] = src[(size_t)(threadIdx.y + i) * NCODE + threadIdx.x];
    __syncthreads();
    size_t obase = (size_t)k0 * DIM + d0;
    #pragma unroll
    for (int i = 0; i < 32; i += 8) {
        float v = t[threadIdx.x][threadIdx.y + i];
        size_t o = obase + (size_t)(threadIdx.y + i) * DIM + threadIdx.x;
        g_ebtf[o] = v;
        g_ebt[o]  = __float2bfloat16(v);
    }
}

// ---------------------------------------------------------------------------
// Stage 1+2 FUSED: bf16 mma.sync scoring (R13 core: M=128, 16 warps, grid
// 512) + in-kernel candidate merge + in-kernel exact fp32 rescore.
// (byte-identical to the passing R16 kernel)
// ---------------------------------------------------------------------------
#define LDA      528
#define S_A      0
#define S_B      67584          // 128*528
#define S_BSZ    67584
#define S_E2     202752         // S_B + 2*S_BSZ (4KB)
#define S_G1     206848         // 128 x ull
#define S_CNT    207872         // 128 x int
#define S_CAND   208384         // 128 x CAP ints (4KB)
#define S_TOTAL  212480
#define XROW     257

__global__ void __launch_bounds__(512, 1)
vq_mma_kernel(const float* __restrict__ x) {
    extern __shared__ char smem[];
    const uint32_t sb  = smem_to_u32(smem);
    const int tid   = threadIdx.x;
    const int lane  = tid & 31;
    const int wid   = tid >> 5;
    const int warpM = wid >> 2;       // 0..3 -> rows warpM*32..+32
    const int warpN = wid & 3;        // 0..3 -> cols warpN*32..+32 per iter
    const int tok0  = blockIdx.x << 7;

    float* e2s = (float*)(smem + S_E2);
    unsigned long long* sG1 = (unsigned long long*)(smem + S_G1);
    int* scnt  = (int*)(smem + S_CNT);
    int (*scand)[CAP] = (int (*)[CAP])(smem + S_CAND);
    float* xs32 = (float*)smem;       // staged fp32 x, [row * XROW + d]

    // async-load B subtile 'sub' (128 codes x 256 bf16) into buffer
    auto load_B = [&](int buf, int sub) {
        const char* src = (const char*)(g_ebt + ((size_t)sub << 7) * DIM);
        uint32_t dst = sb + S_B + buf * S_BSZ;
        #pragma unroll
        for (int j = 0; j < 8; ++j) {
            int idx = tid + (j << 9);     // 0..4095 16B chunks
            int r = idx >> 5, c = idx & 31;
            cp16(dst + r * LDA + c * 16, src + r * 512 + c * 16);
        }
    };
    load_B(0, 0);
    CP_COMMIT();                        // group0 = B0

    // A tile: fused transpose-quantize x (NCHW fp32) -> smem [token][d] bf16.
    const int bimg = tok0 >> 12;
    const int hwb  = tok0 & 4095;
    const float* xb = x + (size_t)bimg * DIM * HW + hwb;
    {
        #pragma unroll
        for (int j = 0; j < 4; ++j) {
            int bb = tid + (j << 9);
            int x1 = bb & 7, x2 = (bb >> 3) & 3, x3 = (bb >> 5) & 15, x4 = bb >> 9;
            int h0 = 4 * x1 + 32 * x4;     // token-local row
            int d0 = 4 * x2 + 16 * x3;     // channel
            float4 v[4];
            #pragma unroll
            for (int i = 0; i < 4; ++i)
                v[i] = *(const float4*)(xb + (size_t)(d0 + i) * HW + h0);
            #pragma unroll
            for (int r = 0; r < 4; ++r) {
                float f0 = (r == 0) ? v[0].x : (r == 1) ? v[0].y : (r == 2) ? v[0].z : v[0].w;
                float f1 = (r == 0) ? v[1].x : (r == 1) ? v[1].y : (r == 2) ? v[1].z : v[1].w;
                float f2 = (r == 0) ? v[2].x : (r == 1) ? v[2].y : (r == 2) ? v[2].z : v[2].w;
                float f3 = (r == 0) ? v[3].x : (r == 1) ? v[3].y : (r == 2) ? v[3].z : v[3].w;
                uint2 pk;
                pk.x = (uint32_t)bf16bits(f0) | ((uint32_t)bf16bits(f1) << 16);
                pk.y = (uint32_t)bf16bits(f2) | ((uint32_t)bf16bits(f3) << 16);
                *(uint2*)(smem + S_A + (h0 + r) * LDA + d0 * 2) = pk;
            }
        }
    }

    #pragma unroll
    for (int j = 0; j < 2; ++j) e2s[tid + (j << 9)] = g_e2[tid + (j << 9)];
    if (tid < 128) sG1[tid] = 0xFFFFFFFFFFFFFFFFull;

    // per-thread top-2 per row-slot (4 slots: 2 mtiles x 2 row-halves)
    float b1v[4], b2v[4];
    int   k1v[4], k2v[4];
    #pragma unroll
    for (int s = 0; s < 4; ++s) { b1v[s] = 3.4e38f; b2v[s] = 3.4e38f; k1v[s] = 0; k2v[s] = 0; }

    // ldmatrix lane addressing (identical fragment mapping to validated rounds)
    uint32_t aA[2];
    #pragma unroll
    for (int mt = 0; mt < 2; ++mt)
        aA[mt] = sb + S_A
               + (uint32_t)((warpM * 32 + mt * 16 + (lane & 15)) * LDA)
               + (uint32_t)((lane >> 4) * 16);
    const uint32_t bRowOff =
        (uint32_t)((warpN * 32 + ((lane >> 4) & 1) * 8 + (lane & 7)) * LDA)
        + (uint32_t)(((lane >> 3) & 1) * 16);

    #pragma unroll 1
    for (int it = 0; it < 8; ++it) {
        int buf = it & 1;
        if (it + 1 < 8) { load_B(buf ^ 1, it + 1); CP_COMMIT(); CP_WAIT(1); }
        else            { CP_WAIT(0); }
        __syncthreads();

        float c[2][4][4];
        #pragma unroll
        for (int mt = 0; mt < 2; ++mt)
            #pragma unroll
            for (int nt = 0; nt < 4; ++nt)
                #pragma unroll
                for (int e = 0; e < 4; ++e) c[mt][nt][e] = 0.f;

        const uint32_t bBase = sb + S_B + buf * S_BSZ + bRowOff;

        #pragma unroll 4
        for (int k = 0; k < 256; k += 16) {
            uint32_t a[2][4];
            #pragma unroll
            for (int mt = 0; mt < 2; ++mt)
                ldsm_x4(a[mt][0], a[mt][1], a[mt][2], a[mt][3],
                        aA[mt] + (uint32_t)(k * 2));
            uint32_t b[4][2];
            #pragma unroll
            for (int p = 0; p < 2; ++p) {
                uint32_t r0, r1, r2, r3;
                ldsm_x4(r0, r1, r2, r3,
                        bBase + (uint32_t)(p * 16 * LDA) + (uint32_t)(k * 2));
                b[2 * p][0] = r0; b[2 * p][1] = r1;
                b[2 * p + 1][0] = r2; b[2 * p + 1][1] = r3;
            }
            #pragma unroll
            for (int mt = 0; mt < 2; ++mt)
                #pragma unroll
                for (int nt = 0; nt < 4; ++nt)
                    mma_bf16(c[mt][nt], a[mt], b[nt]);
        }

        // epilogue: fold scores into per-thread top-2 per row slot
        #pragma unroll
        for (int mt = 0; mt < 2; ++mt)
            #pragma unroll
            for (int nt = 0; nt < 4; ++nt)
                #pragma unroll
                for (int e = 0; e < 4; ++e) {
                    const int s   = mt * 2 + (e >> 1);
                    const int col = (it << 7) + warpN * 32 + nt * 8
                                  + 2 * (lane & 3) + (e & 1);
                    float sc = fmaf(-2.f, c[mt][nt][e], e2s[col]);
                    if (sc < b2v[s]) {
                        if (sc < b1v[s]) {
                            b2v[s] = b1v[s]; k2v[s] = k1v[s];
                            b1v[s] = sc;     k1v[s] = col;
                        } else { b2v[s] = sc; k2v[s] = col; }
                    }
                }
        __syncthreads();   // all warps done reading buf (and A on last iter)
    }

    // ---- Block-exact merge across the 16 owners of each token row ----
    #pragma unroll
    for (int s = 0; s < 4; ++s) {
        const int lt = warpM * 32 + (s >> 1) * 16 + (s & 1) * 8 + (lane >> 2);
        atomicMin(&sG1[lt], packsc(b1v[s], k1v[s]));
    }
    __syncthreads();
    if (tid < 128) {
        scand[tid][0] = (int)(sG1[tid] & 0xFFFFFFFFull);
        scnt[tid] = 1;
    }
    __syncthreads();
    #pragma unroll
    for (int s = 0; s < 4; ++s) {
        const int lt  = warpM * 32 + (s >> 1) * 16 + (s & 1) * 8 + (lane >> 2);
        unsigned long long g = sG1[lt];
        int   gk = (int)(g & 0xFFFFFFFFull);
        float gv = unkeyf((unsigned)(g >> 32));
        if (k1v[s] != gk && b1v[s] < gv + DELTA) {
            int p = atomicAdd(&scnt[lt], 1);
            if (p < CAP) scand[lt][p] = k1v[s];
        }
        if (b2v[s] < gv + DELTA) {
            int p = atomicAdd(&scnt[lt], 1);
            if (p < CAP) scand[lt][p] = k2v[s];
        }
    }
    __syncthreads();

    // ---- Fused exact rescore (R13 arithmetic) ----
    {
        const int rg    = wid & 3;
        const int row   = rg * 32 + lane;
        const bool need = (scnt[row] > 1);
        const int dbase = (wid >> 2) * 64;
        if (need) {
            #pragma unroll 8
            for (int j = 0; j < 64; ++j) {
                int d = dbase + j;
                xs32[row * XROW + d] = xb[(size_t)d * HW + rg * 32 + lane];
            }
        }
    }
    __syncthreads();

    // warp per token: warp w handles tokens w*8 .. w*8+7
    #pragma unroll 1
    for (int t = 0; t < 8; ++t) {
        const int lt  = (wid << 3) + t;
        const int tok = tok0 + lt;
        int n = scnt[lt];
        if (n > CAP) n = CAP;
        if (n <= 1) {
            if (lane == 0) g_ind[tok] = scand[lt][0];
            continue;
        }
        float bs = 3.4e38f;
        int   bk = 0x7fffffff;
        #pragma unroll 1
        for (int i = 0; i < n; ++i) {
            int k = scand[lt][i];
            const float* er = g_ebtf + (size_t)k * DIM;
            float acc = 0.f;
            #pragma unroll
            for (int j = 0; j < 8; ++j)
                acc = fmaf(xs32[lt * XROW + lane + (j << 5)], er[lane + (j << 5)], acc);
            #pragma unroll
            for (int off = 16; off > 0; off >>= 1)
                acc += __shfl_xor_sync(0xffffffffu, acc, off);
            float s = fmaf(-2.f, acc, e2s[k]);
            if (s < bs || (s == bs && k < bk)) { bs = s; bk = k; }
        }
        if (lane == 0) g_ind[tok] = bk;
    }
}

// ---------------------------------------------------------------------------
// Kernel C v2: gather + loss, L1-op minimized.
// Warp covers 128 consecutive NCHW elements (never crosses a d boundary).
// int4 index load; stores realigned via shfl so the misaligned (d_out+1)
// output is written with 31 aligned STG.128 + 4 STG.32 per warp.
// ---------------------------------------------------------------------------
__global__ void __launch_bounds__(256)
gather_kernel(const float* __restrict__ x, const float* __restrict__ embed,
              float* __restrict__ outImg, float* __restrict__ outLoss,
              int misaligned) {
    const int wid = threadIdx.x >> 5, lid = threadIdx.x & 31;
    const size_t ew = (((size_t)blockIdx.x << 3) + wid) << 7;  // warp base elem
    const size_t e  = ew + ((size_t)lid << 2);                 // lane base elem

    int n   = (int)(e >> 20);
    int rem = (int)(e & 1048575);
    int d   = rem >> 12;
    int hw  = rem & 4095;
    int tok = (n << 12) + hw;

    int4 ind = *(const int4*)&g_ind[tok];        // tok % 4 == 0, 16B aligned
    const float* erow = embed + d * NCODE;
    float q0 = erow[ind.x];
    float q1 = erow[ind.y];
    float q2 = erow[ind.z];
    float q3 = erow[ind.w];

    float4 xv = *(const float4*)(x + e);

    if (misaligned) {
        // shifted aligned stores: lane l stores {q3_l, q0_{l+1}, q1_{l+1}, q2_{l+1}}
        float nq0 = __shfl_down_sync(0xffffffffu, q0, 1);
        float nq1 = __shfl_down_sync(0xffffffffu, q1, 1);
        float nq2 = __shfl_down_sync(0xffffffffu, q2, 1);
        if (lid < 31) {
            *(float4*)(outImg + e + 3) = make_float4(q3, nq0, nq1, nq2);
        } else {
            outImg[e + 3] = q3;                  // element ew+127
        }
        if (lid == 0) {                          // elements ew+0..2
            outImg[ew + 0] = q0;
            outImg[ew + 1] = q1;
            outImg[ew + 2] = q2;
        }
    } else {
        *(float4*)(outImg + e) = make_float4(q0, q1, q2, q3);
    }

    float d0 = q0 - xv.x, d1 = q1 - xv.y, d2 = q2 - xv.z, d3 = q3 - xv.w;
    float local = d0 * d0 + d1 * d1 + d2 * d2 + d3 * d3;

    #pragma unroll
    for (int off = 16; off > 0; off >>= 1)
        local += __shfl_down_sync(0xffffffffu, local, off);
    __shared__ float warpsum[8];
    if (lid == 0) warpsum[wid] = local;
    __syncthreads();
    if (threadIdx.x == 0) {
        float s = 0.f;
        #pragma unroll
        for (int w = 0; w < 8; ++w) s += warpsum[w];
        atomicAdd(&g_loss, (double)s);
        __threadfence();
        unsigned t = atomicInc(&g_done, 0xffffffffu);
        if (t == NGATHER - 1 && outLoss) {
            double total = atomicAdd(&g_loss, 0.0);   // ordered read
            outLoss[0] = (float)(0.25 * total / (double)IMG_ELEMS);
        }
    }
}

// ---------------------------------------------------------------------------
extern "C" void kernel_launch(void* const* d_in, const int* in_sizes, int n_in,
                              void* d_out, int out_size) {
    const float* x     = (const float*)d_in[0];   // [16,256,64,64] fp32
    const float* embed = (const float*)d_in[1];   // [256,1024] fp32
    float* out = (float*)d_out;

    int off = out_size - IMG_ELEMS;               // expected 1 (loss scalar first)
    float* outImg  = out + (off > 0 ? off : 0);
    float* outLoss = (off > 0) ? out : nullptr;
    int misaligned = ((off > 0 ? off : 0) & 3) != 0;

    cudaFuncSetAttribute(vq_mma_kernel,
                         cudaFuncAttributeMaxDynamicSharedMemorySize, S_TOTAL);

    e2_kernel<<<NCODE / 256, 256>>>(embed);
    prep_e_kernel<<<dim3(NCODE / 32, DIM / 32, 1), dim3(32, 8)>>>(embed);
    vq_mma_kernel<<<NTOK / 128, 512, S_TOTAL>>>(x);
    gather_kernel<<<NGATHER, 256>>>(x, embed, outImg, outLoss, misaligned);
}